// round 2
// baseline (speedup 1.0000x reference)
#include <cuda_runtime.h>
#include <math.h>

// Problem constants (fixed shapes per reference setup_inputs)
#define H    128          // MEM_DIM
#define MSG  256          // MSG_DIM
#define G3   (3 * H)      // 384 gate outputs
#define BM   32           // rows per block
#define BK   8            // k-chunk

// Transposed weights: Wt[k][j] = W[j][k], row-major [K][384]
__device__ float g_Wt_ih[MSG * G3];   // 256*384 = 98304 floats (384KB)
__device__ float g_Wt_hh[H   * G3];   // 128*384 = 49152 floats (192KB)

// ---------------------------------------------------------------------------
// Weight transpose (runs every launch; trivial cost, keeps graph deterministic)
// ---------------------------------------------------------------------------
__global__ void transpose_w_kernel(const float* __restrict__ W_ih,
                                   const float* __restrict__ W_hh) {
    int o = blockIdx.x * blockDim.x + threadIdx.x;
    const int n1 = MSG * G3;
    const int n2 = H * G3;
    if (o < n1) {
        int k = o / G3, j = o - k * G3;
        g_Wt_ih[o] = W_ih[j * MSG + k];
    } else if (o < n1 + n2) {
        int p = o - n1;
        int k = p / G3, j = p - k * G3;
        g_Wt_hh[p] = W_hh[j * H + k];
    }
}

// ---------------------------------------------------------------------------
// Bulk copy (float4 grid-stride)
// ---------------------------------------------------------------------------
__global__ void copy_f4_kernel(const float4* __restrict__ src,
                               float4* __restrict__ dst, long n4) {
    long i = (long)blockIdx.x * blockDim.x + threadIdx.x;
    long stride = (long)gridDim.x * blockDim.x;
    for (; i < n4; i += stride) dst[i] = src[i];
}

// ---------------------------------------------------------------------------
// Fused GRU update + scatter.
// Block: 32 rows x 384 gate-cols. 256 threads (ty=tid/32 -> 4 rows,
// tx=tid%32 -> column quad j=tx*4 in EACH of the 3 gates).
// Epilogue is fully thread-local: r, z, i_n, h_n for column j all live in
// this thread's accumulators.
// ---------------------------------------------------------------------------
__global__ __launch_bounds__(256)
void gru_update_kernel(const float* __restrict__ memory,
                       const int*   __restrict__ node_ids,
                       const float* __restrict__ X,       // unique_messages
                       const float* __restrict__ ts,      // timestamps
                       const float* __restrict__ b_ih,
                       const float* __restrict__ b_hh,
                       float* __restrict__ out_mem,
                       float* __restrict__ out_lu,
                       int B)
{
    __shared__ float sA[BK * BM];        // 1 KB   A-tile (transposed: [kk][row])
    __shared__ float sB[BK * G3];        // 12 KB  W-tile ([kk][384])
    __shared__ int   s_nodes[BM];

    const int tid = threadIdx.x;
    const int tx  = tid & 31;
    const int ty  = tid >> 5;
    const int row0 = blockIdx.x * BM;

    if (tid < BM) {
        int r = row0 + tid;
        s_nodes[tid] = (r < B) ? node_ids[r] : 0;
    }
    __syncthreads();

    float4 accI[4][3];   // GI = x @ W_ih^T   (rows i, gates g)
    float4 accH[4][3];   // GH = h @ W_hh^T
    #pragma unroll
    for (int i = 0; i < 4; i++)
        #pragma unroll
        for (int g = 0; g < 3; g++) {
            accI[i][g] = make_float4(0.f, 0.f, 0.f, 0.f);
            accH[i][g] = make_float4(0.f, 0.f, 0.f, 0.f);
        }

    const int ld_r  = tid & (BM - 1);    // row within tile for A loads
    const int ld_kk = tid >> 5;          // k within chunk  for A loads

    // ---------------- Phase 1: GI over K = MSG (messages x W_ih^T) -----------
    for (int k0 = 0; k0 < MSG; k0 += BK) {
        {   // A: sA[kk][r] = X[row][k0+kk]
            int row = row0 + ld_r;
            if (row >= B) row = B - 1;
            sA[ld_kk * BM + ld_r] = X[(long)row * MSG + k0 + ld_kk];
        }
        {   // B: contiguous copy of 8 rows of g_Wt_ih (3072 floats)
            const float4* src = (const float4*)(g_Wt_ih + k0 * G3);
            float4* dst = (float4*)sB;
            #pragma unroll
            for (int i = 0; i < 3; i++) dst[tid + i * 256] = src[tid + i * 256];
        }
        __syncthreads();
        #pragma unroll
        for (int kk = 0; kk < BK; kk++) {
            float4 a  = *(const float4*)(sA + kk * BM + ty * 4);
            float4 b0 = *(const float4*)(sB + kk * G3 + 0 * H + tx * 4);
            float4 b1 = *(const float4*)(sB + kk * G3 + 1 * H + tx * 4);
            float4 b2 = *(const float4*)(sB + kk * G3 + 2 * H + tx * 4);
            float as[4] = {a.x, a.y, a.z, a.w};
            #pragma unroll
            for (int i = 0; i < 4; i++) {
                float s = as[i];
                accI[i][0].x += s * b0.x; accI[i][0].y += s * b0.y;
                accI[i][0].z += s * b0.z; accI[i][0].w += s * b0.w;
                accI[i][1].x += s * b1.x; accI[i][1].y += s * b1.y;
                accI[i][1].z += s * b1.z; accI[i][1].w += s * b1.w;
                accI[i][2].x += s * b2.x; accI[i][2].y += s * b2.y;
                accI[i][2].z += s * b2.z; accI[i][2].w += s * b2.w;
            }
        }
        __syncthreads();
    }

    // ---------------- Phase 2: GH over K = H (gathered memory x W_hh^T) ------
    for (int k0 = 0; k0 < H; k0 += BK) {
        {   // A: sA[kk][r] = memory[node[r]][k0+kk]
            int node = s_nodes[ld_r];
            sA[ld_kk * BM + ld_r] = memory[(long)node * H + k0 + ld_kk];
        }
        {
            const float4* src = (const float4*)(g_Wt_hh + k0 * G3);
            float4* dst = (float4*)sB;
            #pragma unroll
            for (int i = 0; i < 3; i++) dst[tid + i * 256] = src[tid + i * 256];
        }
        __syncthreads();
        #pragma unroll
        for (int kk = 0; kk < BK; kk++) {
            float4 a  = *(const float4*)(sA + kk * BM + ty * 4);
            float4 b0 = *(const float4*)(sB + kk * G3 + 0 * H + tx * 4);
            float4 b1 = *(const float4*)(sB + kk * G3 + 1 * H + tx * 4);
            float4 b2 = *(const float4*)(sB + kk * G3 + 2 * H + tx * 4);
            float as[4] = {a.x, a.y, a.z, a.w};
            #pragma unroll
            for (int i = 0; i < 4; i++) {
                float s = as[i];
                accH[i][0].x += s * b0.x; accH[i][0].y += s * b0.y;
                accH[i][0].z += s * b0.z; accH[i][0].w += s * b0.w;
                accH[i][1].x += s * b1.x; accH[i][1].y += s * b1.y;
                accH[i][1].z += s * b1.z; accH[i][1].w += s * b1.w;
                accH[i][2].x += s * b2.x; accH[i][2].y += s * b2.y;
                accH[i][2].z += s * b2.z; accH[i][2].w += s * b2.w;
            }
        }
        __syncthreads();
    }

    // ---------------- Epilogue: gates + scatter ------------------------------
    const int j = tx * 4;
    const float4 bir = *(const float4*)(b_ih + 0 * H + j);
    const float4 biz = *(const float4*)(b_ih + 1 * H + j);
    const float4 bin = *(const float4*)(b_ih + 2 * H + j);
    const float4 bhr = *(const float4*)(b_hh + 0 * H + j);
    const float4 bhz = *(const float4*)(b_hh + 1 * H + j);
    const float4 bhn = *(const float4*)(b_hh + 2 * H + j);

    #pragma unroll
    for (int i = 0; i < 4; i++) {
        int row = row0 + ty * 4 + i;
        if (row < B) {
            int node = s_nodes[ty * 4 + i];
            float4 h = *(const float4*)(memory + (long)node * H + j);

            float hv[4] = {h.x, h.y, h.z, h.w};
            float gr[4] = {accI[i][0].x + accH[i][0].x + bir.x + bhr.x,
                           accI[i][0].y + accH[i][0].y + bir.y + bhr.y,
                           accI[i][0].z + accH[i][0].z + bir.z + bhr.z,
                           accI[i][0].w + accH[i][0].w + bir.w + bhr.w};
            float gz[4] = {accI[i][1].x + accH[i][1].x + biz.x + bhz.x,
                           accI[i][1].y + accH[i][1].y + biz.y + bhz.y,
                           accI[i][1].z + accH[i][1].z + biz.z + bhz.z,
                           accI[i][1].w + accH[i][1].w + biz.w + bhz.w};
            float gin[4] = {accI[i][2].x + bin.x, accI[i][2].y + bin.y,
                            accI[i][2].z + bin.z, accI[i][2].w + bin.w};
            float ghn[4] = {accH[i][2].x + bhn.x, accH[i][2].y + bhn.y,
                            accH[i][2].z + bhn.z, accH[i][2].w + bhn.w};

            float o[4];
            #pragma unroll
            for (int c = 0; c < 4; c++) {
                float r = 1.0f / (1.0f + __expf(-gr[c]));
                float z = 1.0f / (1.0f + __expf(-gz[c]));
                float n = tanhf(gin[c] + r * ghn[c]);
                o[c] = (1.0f - z) * n + z * hv[c];
            }
            float4 ov = make_float4(o[0], o[1], o[2], o[3]);
            *(float4*)(out_mem + (long)node * H + j) = ov;
        }
    }

    // last_update scatter: one thread per row
    if (tid < BM) {
        int row = row0 + tid;
        if (row < B) out_lu[s_nodes[tid]] = ts[row];
    }
}

// ---------------------------------------------------------------------------
// Launch: inputs in metadata order:
//   0 memory [N,128] f32 | 1 last_update [N] f32 | 2 unique_node_ids [B] i32
//   3 unique_messages [B,256] f32 | 4 timestamps [B] f32
//   5 W_ih [384,256] | 6 W_hh [384,128] | 7 b_ih [384] | 8 b_hh [384]
// Output: concat(updated_memory [N*128], updated_last_update [N]) f32
// ---------------------------------------------------------------------------
extern "C" void kernel_launch(void* const* d_in, const int* in_sizes, int n_in,
                              void* d_out, int out_size) {
    const float* memory      = (const float*)d_in[0];
    const float* last_update = (const float*)d_in[1];
    const int*   node_ids    = (const int*)  d_in[2];
    const float* X           = (const float*)d_in[3];
    const float* ts          = (const float*)d_in[4];
    const float* W_ih        = (const float*)d_in[5];
    const float* W_hh        = (const float*)d_in[6];
    const float* b_ih        = (const float*)d_in[7];
    const float* b_hh        = (const float*)d_in[8];

    const int n_nodes = in_sizes[1];       // 1,000,000
    const int B       = in_sizes[2];       // 200,000

    float* out_mem = (float*)d_out;
    float* out_lu  = out_mem + (long)n_nodes * H;

    // 1) transpose weights into device scratch
    {
        int nt = (MSG + H) * G3;
        transpose_w_kernel<<<(nt + 255) / 256, 256>>>(W_ih, W_hh);
    }
    // 2) clone memory -> out
    {
        long n4 = (long)n_nodes * H / 4;
        int blocks = 16384;
        copy_f4_kernel<<<blocks, 256>>>((const float4*)memory,
                                        (float4*)out_mem, n4);
    }
    // 3) clone last_update -> out tail
    {
        long n4 = (long)n_nodes / 4;
        int blocks = (int)((n4 + 255) / 256);
        copy_f4_kernel<<<blocks, 256>>>((const float4*)last_update,
                                        (float4*)out_lu, n4);
    }
    // 4) fused GRU + scatter (overwrites the cloned rows; same-stream order
    //    guarantees the clone is complete first)
    {
        int blocks = (B + BM - 1) / BM;
        gru_update_kernel<<<blocks, 256>>>(memory, node_ids, X, ts,
                                           b_ih, b_hh, out_mem, out_lu, B);
    }
}

// round 5
// speedup vs baseline: 3.2455x; 3.2455x over previous
#include <cuda_runtime.h>
#include <cstdint>
#include <math.h>

// ---------------------------------------------------------------------------
// Problem constants
// ---------------------------------------------------------------------------
#define H     128        // MEM_DIM
#define MSG   256        // MSG_DIM
#define BM    64         // rows per CTA
#define BK    16         // K elems per chunk
#define NCH   24         // 16 chunks X (K=256) + 8 chunks H (K=128)
#define NTHREADS 512

// smem float-index offsets
#define SA0   0                    // 64 x 20
#define SA1   1280
#define SB0   2560                 // 384 x 20
#define SB1   10240
#define SDO   0                    // epilogue D stage: 64 x 520 (reuses A/B)
#define SD_STRIDE 520
#define NODES_OFF 33280            // 64 ints
#define BRZ_OFF   33344            // 256
#define BIN_OFF   33600            // 128
#define BHN_OFF   33728            // 128
#define SMEM_FLOATS 33856
#define SMEM_BYTES  (SMEM_FLOATS * 4)

__device__ __forceinline__ uint32_t f2tf32(float x) {
    uint32_t r;
    asm("cvt.rna.tf32.f32 %0, %1;" : "=r"(r) : "f"(x));
    return r;
}

__device__ __forceinline__ void mma_tf32(float* d, const uint32_t* a,
                                         uint32_t b0, uint32_t b1) {
    asm volatile(
        "mma.sync.aligned.m16n8k8.row.col.f32.tf32.tf32.f32 "
        "{%0,%1,%2,%3}, {%4,%5,%6,%7}, {%8,%9}, {%0,%1,%2,%3};"
        : "+f"(d[0]), "+f"(d[1]), "+f"(d[2]), "+f"(d[3])
        : "r"(a[0]), "r"(a[1]), "r"(a[2]), "r"(a[3]), "r"(b0), "r"(b1));
}

// ---------------------------------------------------------------------------
// Bulk copy (float4 grid-stride)
// ---------------------------------------------------------------------------
__global__ void copy_f4_kernel(const float4* __restrict__ src,
                               float4* __restrict__ dst, long n4) {
    long i = (long)blockIdx.x * blockDim.x + threadIdx.x;
    long stride = (long)gridDim.x * blockDim.x;
    for (; i < n4; i += stride) dst[i] = src[i];
}

// ---------------------------------------------------------------------------
// Fused GRU update via mma.sync tf32
// ---------------------------------------------------------------------------
__global__ __launch_bounds__(NTHREADS, 1)
void gru_mma_kernel(const float* __restrict__ memory,
                    const int*   __restrict__ node_ids,
                    const float* __restrict__ X,
                    const float* __restrict__ ts,
                    const float* __restrict__ W_ih,   // [384,256] K-major
                    const float* __restrict__ W_hh,   // [384,128] K-major
                    const float* __restrict__ b_ih,
                    const float* __restrict__ b_hh,
                    float* __restrict__ out_mem,
                    float* __restrict__ out_lu,
                    int B)
{
    extern __shared__ float sm[];
    int*   s_nodes = (int*)(sm + NODES_OFF);
    float* s_brz   = sm + BRZ_OFF;
    float* s_bin   = sm + BIN_OFF;
    float* s_bhn   = sm + BHN_OFF;

    const int tid  = threadIdx.x;
    const int lane = tid & 31;
    const int wid  = tid >> 5;
    const int wm   = wid >> 3;          // 0..1 : 32-row slab
    const int wn   = wid & 7;           // 0..7 : 32 rz cols + 16 n cols
    const int gid  = lane >> 2;         // 0..7
    const int tig  = lane & 3;          // 0..3
    const int row0 = blockIdx.x * BM;

    if (tid < BM) {
        int r = row0 + tid;
        s_nodes[tid] = node_ids[r < B ? r : (B - 1)];
    }
    if (tid < 256) s_brz[tid] = b_ih[tid] + b_hh[tid];
    else if (tid < 384) s_bin[tid - 256] = b_ih[tid];   // b_ih[256..383]
    else { int j = tid - 384; s_bhn[j] = b_hh[256 + j]; }
    __syncthreads();

    // accumulators
    float acc_rz[2][4][4];        // [m16 tile][rz n8 tile][frag]
    float acc_n [2][2][2][4];     // [phase][m16 tile][n n8 tile][frag]
    #pragma unroll
    for (int t = 0; t < 2; t++) {
        #pragma unroll
        for (int nt = 0; nt < 4; nt++)
            #pragma unroll
            for (int j = 0; j < 4; j++) acc_rz[t][nt][j] = 0.f;
        #pragma unroll
        for (int ph = 0; ph < 2; ph++)
            #pragma unroll
            for (int nt = 0; nt < 2; nt++)
                #pragma unroll
                for (int j = 0; j < 4; j++) acc_n[ph][t][nt][j] = 0.f;
    }

    // fill indexing
    const int a_r  = tid >> 2, a_q = tid & 3;         // tid<256: A row/quad
    float4 pa;                                        // prefetch regs
    float4 pb[3];

    // ---- prefetch loader ----
    auto load_chunk = [&](int c) {
        if (c < 16) {
            const int k0 = c * BK;
            if (tid < 256) {
                int gr = row0 + a_r; if (gr >= B) gr = B - 1;
                pa = *(const float4*)(X + (long)gr * MSG + k0 + a_q * 4);
            }
            #pragma unroll
            for (int i = 0; i < 3; i++) {
                int idx = tid + i * NTHREADS;
                int r = idx >> 2, q = idx & 3;
                pb[i] = *(const float4*)(W_ih + (long)r * MSG + k0 + q * 4);
            }
        } else {
            const int k0 = (c - 16) * BK;
            if (tid < 256) {
                int node = s_nodes[a_r];
                pa = *(const float4*)(memory + (long)node * H + k0 + a_q * 4);
            }
            #pragma unroll
            for (int i = 0; i < 3; i++) {
                int idx = tid + i * NTHREADS;
                int r = idx >> 2, q = idx & 3;
                pb[i] = *(const float4*)(W_hh + (long)r * H + k0 + q * 4);
            }
        }
    };
    auto store_chunk = [&](int s) {
        float* sA = sm + (s ? SA1 : SA0);
        float* sB = sm + (s ? SB1 : SB0);
        if (tid < 256) {
            uint32_t* p = (uint32_t*)(sA + a_r * 20 + a_q * 4);
            uint4 v = make_uint4(f2tf32(pa.x), f2tf32(pa.y), f2tf32(pa.z), f2tf32(pa.w));
            *(uint4*)p = v;
        }
        #pragma unroll
        for (int i = 0; i < 3; i++) {
            int idx = tid + i * NTHREADS;
            int r = idx >> 2, q = idx & 3;
            uint4 v = make_uint4(f2tf32(pb[i].x), f2tf32(pb[i].y),
                                 f2tf32(pb[i].z), f2tf32(pb[i].w));
            *(uint4*)((uint32_t*)(sB + r * 20 + q * 4)) = v;
        }
    };

    // ---- mainloop ----
    load_chunk(0);
    store_chunk(0);
    __syncthreads();

    for (int c = 0; c < NCH; c++) {
        if (c + 1 < NCH) load_chunk(c + 1);

        const int s = c & 1;
        const uint32_t* sA = (const uint32_t*)(sm + (s ? SA1 : SA0));
        const uint32_t* sB = (const uint32_t*)(sm + (s ? SB1 : SB0));
        const int ph = (c < 16) ? 0 : 1;

        #pragma unroll
        for (int k0 = 0; k0 < BK; k0 += 8) {
            uint32_t a[2][4];
            #pragma unroll
            for (int t = 0; t < 2; t++) {
                int r = wm * 32 + t * 16 + gid;
                a[t][0] = sA[r * 20 + k0 + tig];
                a[t][1] = sA[(r + 8) * 20 + k0 + tig];
                a[t][2] = sA[r * 20 + k0 + tig + 4];
                a[t][3] = sA[(r + 8) * 20 + k0 + tig + 4];
            }
            #pragma unroll
            for (int nt = 0; nt < 4; nt++) {
                int n = wn * 32 + nt * 8 + gid;
                uint32_t b0 = sB[n * 20 + k0 + tig];
                uint32_t b1 = sB[n * 20 + k0 + tig + 4];
                mma_tf32(acc_rz[0][nt], a[0], b0, b1);
                mma_tf32(acc_rz[1][nt], a[1], b0, b1);
            }
            #pragma unroll
            for (int nt = 0; nt < 2; nt++) {
                int n = 256 + wn * 16 + nt * 8 + gid;
                uint32_t b0 = sB[n * 20 + k0 + tig];
                uint32_t b1 = sB[n * 20 + k0 + tig + 4];
                if (ph == 0) {
                    mma_tf32(acc_n[0][0][nt], a[0], b0, b1);
                    mma_tf32(acc_n[0][1][nt], a[1], b0, b1);
                } else {
                    mma_tf32(acc_n[1][0][nt], a[0], b0, b1);
                    mma_tf32(acc_n[1][1][nt], a[1], b0, b1);
                }
            }
        }

        if (c + 1 < NCH) {
            store_chunk((c + 1) & 1);
            __syncthreads();
        }
    }

    // ---- stage D to smem (reuses A/B buffers) ----
    __syncthreads();
    #pragma unroll
    for (int t = 0; t < 2; t++) {
        int r = wm * 32 + t * 16 + gid;
        #pragma unroll
        for (int nt = 0; nt < 4; nt++) {
            int cc = wn * 32 + nt * 8 + tig * 2;
            *(float2*)(sm + SDO + r * SD_STRIDE + cc)       =
                make_float2(acc_rz[t][nt][0], acc_rz[t][nt][1]);
            *(float2*)(sm + SDO + (r + 8) * SD_STRIDE + cc) =
                make_float2(acc_rz[t][nt][2], acc_rz[t][nt][3]);
        }
        #pragma unroll
        for (int ph = 0; ph < 2; ph++)
            #pragma unroll
            for (int nt = 0; nt < 2; nt++) {
                int cc = 256 + ph * 128 + wn * 16 + nt * 8 + tig * 2;
                *(float2*)(sm + SDO + r * SD_STRIDE + cc)       =
                    make_float2(acc_n[ph][t][nt][0], acc_n[ph][t][nt][1]);
                *(float2*)(sm + SDO + (r + 8) * SD_STRIDE + cc) =
                    make_float2(acc_n[ph][t][nt][2], acc_n[ph][t][nt][3]);
            }
    }
    __syncthreads();

    // ---- epilogue: gates + scatter ----
    #pragma unroll
    for (int i = 0; i < 4; i++) {
        int idx = tid + i * NTHREADS;        // 2048 tasks: 64 rows x 32 quads
        int r  = idx >> 5;
        int hc = (idx & 31) * 4;
        int gr = row0 + r;
        if (gr < B) {
            int node = s_nodes[r];
            const float* dr = sm + SDO + r * SD_STRIDE;
            float4 rrv = *(const float4*)(dr + hc);
            float4 zzv = *(const float4*)(dr + 128 + hc);
            float4 inv = *(const float4*)(dr + 256 + hc);
            float4 hnv = *(const float4*)(dr + 384 + hc);
            float4 hv  = *(const float4*)(memory + (long)node * H + hc);

            float rr[4] = {rrv.x, rrv.y, rrv.z, rrv.w};
            float zz[4] = {zzv.x, zzv.y, zzv.z, zzv.w};
            float nn[4] = {inv.x, inv.y, inv.z, inv.w};
            float nh[4] = {hnv.x, hnv.y, hnv.z, hnv.w};
            float hh[4] = {hv.x, hv.y, hv.z, hv.w};
            float o[4];
            #pragma unroll
            for (int j = 0; j < 4; j++) {
                float rg = 1.0f / (1.0f + __expf(-(rr[j] + s_brz[hc + j])));
                float zg = 1.0f / (1.0f + __expf(-(zz[j] + s_brz[128 + hc + j])));
                float ng = tanhf(nn[j] + s_bin[hc + j] + rg * (nh[j] + s_bhn[hc + j]));
                o[j] = (1.0f - zg) * ng + zg * hh[j];
            }
            *(float4*)(out_mem + (long)node * H + hc) = make_float4(o[0], o[1], o[2], o[3]);
        }
    }

    if (tid < BM) {
        int r = row0 + tid;
        if (r < B) out_lu[s_nodes[tid]] = ts[r];
    }
}

// ---------------------------------------------------------------------------
// Launch. Inputs (metadata order):
//   0 memory [N,128] | 1 last_update [N] | 2 unique_node_ids [B] i32
//   3 unique_messages [B,256] | 4 timestamps [B]
//   5 W_ih [384,256] | 6 W_hh [384,128] | 7 b_ih [384] | 8 b_hh [384]
// Output: concat(updated_memory [N*128], updated_last_update [N]) f32
// ---------------------------------------------------------------------------
extern "C" void kernel_launch(void* const* d_in, const int* in_sizes, int n_in,
                              void* d_out, int out_size) {
    const float* memory      = (const float*)d_in[0];
    const float* last_update = (const float*)d_in[1];
    const int*   node_ids    = (const int*)  d_in[2];
    const float* X           = (const float*)d_in[3];
    const float* ts          = (const float*)d_in[4];
    const float* W_ih        = (const float*)d_in[5];
    const float* W_hh        = (const float*)d_in[6];
    const float* b_ih        = (const float*)d_in[7];
    const float* b_hh        = (const float*)d_in[8];

    const int n_nodes = in_sizes[1];
    const int B       = in_sizes[2];

    float* out_mem = (float*)d_out;
    float* out_lu  = out_mem + (long)n_nodes * H;

    // clone memory -> out
    {
        long n4 = (long)n_nodes * H / 4;
        copy_f4_kernel<<<16384, 256>>>((const float4*)memory, (float4*)out_mem, n4);
    }
    // clone last_update -> out tail
    {
        long n4 = (long)n_nodes / 4;
        copy_f4_kernel<<<(int)((n4 + 255) / 256), 256>>>((const float4*)last_update,
                                                         (float4*)out_lu, n4);
    }
    // fused tf32 mma GRU + scatter
    {
        cudaFuncSetAttribute(gru_mma_kernel,
                             cudaFuncAttributeMaxDynamicSharedMemorySize, SMEM_BYTES);
        int blocks = (B + BM - 1) / BM;
        gru_mma_kernel<<<blocks, NTHREADS, SMEM_BYTES>>>(memory, node_ids, X, ts,
                                                         W_ih, W_hh, b_ih, b_hh,
                                                         out_mem, out_lu, B);
    }
}

// round 6
// speedup vs baseline: 4.2571x; 1.3117x over previous
#include <cuda_runtime.h>
#include <cuda_fp16.h>
#include <cstdint>
#include <math.h>

// ---------------------------------------------------------------------------
// Problem constants
// ---------------------------------------------------------------------------
#define H     128        // MEM_DIM
#define MSG   256        // MSG_DIM
#define BM    64         // rows per CTA (B=200000 = 3125 * 64, exact)
#define BKH   32         // K halves per chunk
#define NCH   12         // 8 chunks X (K=256) + 4 chunks H (K=128)
#define NTHREADS 512
#define RSTR  40         // smem row stride in halves (80B: conflict-free ldmatrix)

// smem half-index offsets
#define SA0   0                    // 64  x 40 halves
#define SA1   2560
#define SB0   5120                 // 384 x 40 halves
#define SB1   20480
#define HALF_REGION 35840          // halves (71680 B)
#define NODES_BYTE  71680          // 64 ints
#define BRZ_BYTE    71936          // 256 f32
#define BIN_BYTE    72960          // 128 f32
#define BHN_BYTE    73472          // 128 f32
#define SMEM_BYTES  73984

__device__ __forceinline__ void ldsm_x4(uint32_t* r, uint32_t addr) {
    asm volatile("ldmatrix.sync.aligned.m8n8.x4.shared.b16 {%0,%1,%2,%3}, [%4];"
                 : "=r"(r[0]), "=r"(r[1]), "=r"(r[2]), "=r"(r[3]) : "r"(addr));
}

__device__ __forceinline__ void mma_f16(float* d, const uint32_t* a,
                                        uint32_t b0, uint32_t b1) {
    asm volatile(
        "mma.sync.aligned.m16n8k16.row.col.f32.f16.f16.f32 "
        "{%0,%1,%2,%3}, {%4,%5,%6,%7}, {%8,%9}, {%0,%1,%2,%3};"
        : "+f"(d[0]), "+f"(d[1]), "+f"(d[2]), "+f"(d[3])
        : "r"(a[0]), "r"(a[1]), "r"(a[2]), "r"(a[3]), "r"(b0), "r"(b1));
}

__device__ __forceinline__ uint32_t pack_h2(float x, float y) {
    half2 h = __float22half2_rn(make_float2(x, y));
    return *(uint32_t*)&h;
}

// ---------------------------------------------------------------------------
// Fused clone: memory [N*128] + last_update [N] -> out (single launch)
// ---------------------------------------------------------------------------
__global__ void clone_kernel(const float4* __restrict__ mem_src,
                             float4* __restrict__ mem_dst, long n4m,
                             const float4* __restrict__ lu_src,
                             float4* __restrict__ lu_dst, long n4l) {
    long i = (long)blockIdx.x * blockDim.x + threadIdx.x;
    long stride = (long)gridDim.x * blockDim.x;
    for (long j = i; j < n4m; j += stride) mem_dst[j] = mem_src[j];
    for (long j = i; j < n4l; j += stride) lu_dst[j] = lu_src[j];
}

// ---------------------------------------------------------------------------
// Fused GRU update via mma.sync fp16 (f32 accum), register-local epilogue
// 16 warps: wm = wid>>3 (2 M-slabs of 32), wn = wid&7 (16-col group per gate)
// ---------------------------------------------------------------------------
__global__ __launch_bounds__(NTHREADS, 1)
void gru_mma_kernel(const float* __restrict__ memory,
                    const int*   __restrict__ node_ids,
                    const float* __restrict__ X,
                    const float* __restrict__ ts,
                    const float* __restrict__ W_ih,   // [384,256] K-major
                    const float* __restrict__ W_hh,   // [384,128] K-major
                    const float* __restrict__ b_ih,
                    const float* __restrict__ b_hh,
                    float* __restrict__ out_mem,
                    float* __restrict__ out_lu,
                    int B)
{
    extern __shared__ char smc[];
    half*  smh     = (half*)smc;
    int*   s_nodes = (int*)  (smc + NODES_BYTE);
    float* s_brz   = (float*)(smc + BRZ_BYTE);
    float* s_bin   = (float*)(smc + BIN_BYTE);
    float* s_bhn   = (float*)(smc + BHN_BYTE);
    const uint32_t sh_base = (uint32_t)__cvta_generic_to_shared(smc);

    const int tid  = threadIdx.x;
    const int lane = tid & 31;
    const int wid  = tid >> 5;
    const int wm   = wid >> 3;          // 0..1
    const int wn   = wid & 7;           // 0..7
    const int gid  = lane >> 2;         // 0..7
    const int tig  = lane & 3;          // 0..3
    const int row0 = blockIdx.x * BM;

    if (tid < BM) {
        int r = row0 + tid;
        s_nodes[tid] = node_ids[r < B ? r : (B - 1)];
    }
    if (tid < 256) s_brz[tid] = b_ih[tid] + b_hh[tid];
    else if (tid < 384) s_bin[tid - 256] = b_ih[tid];
    else { int j = tid - 384; s_bhn[j] = b_hh[256 + j]; }
    __syncthreads();

    // accumulators: [m-tile][tile: 0,1=r  2,3=z  4,5=i_n  6,7=h_n][frag]
    float acc[2][8][4];
    #pragma unroll
    for (int t = 0; t < 2; t++)
        #pragma unroll
        for (int g = 0; g < 8; g++)
            #pragma unroll
            for (int j = 0; j < 4; j++) acc[t][g][j] = 0.f;

    // fill indexing: A 512 f4-tasks (1/thread), B 3072 (6/thread)
    const int a_r = tid >> 3, a_q = tid & 7;
    float4 pa, pb[6];

    auto load_chunk = [&](int c) {
        if (c < 8) {
            const int k0 = c * BKH;
            {
                int gr = row0 + a_r; if (gr >= B) gr = B - 1;
                pa = *(const float4*)(X + (long)gr * MSG + k0 + a_q * 4);
            }
            #pragma unroll
            for (int i = 0; i < 6; i++) {
                int idx = tid + i * NTHREADS;
                int r = idx >> 3, q = idx & 7;
                pb[i] = *(const float4*)(W_ih + (long)r * MSG + k0 + q * 4);
            }
        } else {
            const int k0 = (c - 8) * BKH;
            {
                int node = s_nodes[a_r];
                pa = *(const float4*)(memory + (long)node * H + k0 + a_q * 4);
            }
            #pragma unroll
            for (int i = 0; i < 6; i++) {
                int idx = tid + i * NTHREADS;
                int r = idx >> 3, q = idx & 7;
                pb[i] = *(const float4*)(W_hh + (long)r * H + k0 + q * 4);
            }
        }
    };
    auto store_chunk = [&](int s) {
        half* sA = smh + (s ? SA1 : SA0);
        half* sB = smh + (s ? SB1 : SB0);
        *(uint2*)(sA + a_r * RSTR + a_q * 4) =
            make_uint2(pack_h2(pa.x, pa.y), pack_h2(pa.z, pa.w));
        #pragma unroll
        for (int i = 0; i < 6; i++) {
            int idx = tid + i * NTHREADS;
            int r = idx >> 3, q = idx & 7;
            *(uint2*)(sB + r * RSTR + q * 4) =
                make_uint2(pack_h2(pb[i].x, pb[i].y), pack_h2(pb[i].z, pb[i].w));
        }
    };

    load_chunk(0);
    store_chunk(0);
    __syncthreads();

    const int lr = lane & 15;            // ldmatrix row lane
    const int lk = (lane >> 4) * 8;      // ldmatrix k-block (halves)

    for (int c = 0; c < NCH; c++) {
        if (c + 1 < NCH) load_chunk(c + 1);

        const int s  = c & 1;
        const uint32_t baseA = sh_base + (s ? SA1 : SA0) * 2u;
        const uint32_t baseB = sh_base + (s ? SB1 : SB0) * 2u;
        const int nb = (c < 8) ? 4 : 6;  // i_n vs h_n acc bank

        #pragma unroll
        for (int kk = 0; kk < 2; kk++) {
            const uint32_t kof = (kk * 16 + lk) * 2u;
            uint32_t a[2][4], br[4], bz[4], bn[4];
            ldsm_x4(a[0], baseA + (wm * 32 +  0 + lr) * (RSTR * 2u) + kof);
            ldsm_x4(a[1], baseA + (wm * 32 + 16 + lr) * (RSTR * 2u) + kof);
            ldsm_x4(br,   baseB + (      wn * 16 + lr) * (RSTR * 2u) + kof);
            ldsm_x4(bz,   baseB + (128 + wn * 16 + lr) * (RSTR * 2u) + kof);
            ldsm_x4(bn,   baseB + (256 + wn * 16 + lr) * (RSTR * 2u) + kof);
            #pragma unroll
            for (int t = 0; t < 2; t++) {
                mma_f16(acc[t][0],      a[t], br[0], br[2]);
                mma_f16(acc[t][1],      a[t], br[1], br[3]);
                mma_f16(acc[t][2],      a[t], bz[0], bz[2]);
                mma_f16(acc[t][3],      a[t], bz[1], bz[3]);
                mma_f16(acc[t][nb],     a[t], bn[0], bn[2]);
                mma_f16(acc[t][nb + 1], a[t], bn[1], bn[3]);
            }
        }

        if (c + 1 < NCH) {
            store_chunk((c + 1) & 1);
            __syncthreads();
        }
    }

    // ---- register-local epilogue: gates + scatter ----
    #pragma unroll
    for (int t = 0; t < 2; t++) {
        #pragma unroll
        for (int s = 0; s < 2; s++) {
            const int r_local = wm * 32 + t * 16 + gid + s * 8;
            const int grow = row0 + r_local;
            if (grow < B) {
                const int node = s_nodes[r_local];
                #pragma unroll
                for (int nt = 0; nt < 2; nt++) {
                    const int c0 = wn * 16 + nt * 8 + tig * 2;
                    float2 hv = *(const float2*)(memory + (long)node * H + c0);
                    float hh[2] = {hv.x, hv.y};
                    float o[2];
                    #pragma unroll
                    for (int j = 0; j < 2; j++) {
                        const int fi = s * 2 + j;
                        float rg = 1.0f / (1.0f + __expf(-(acc[t][nt][fi]     + s_brz[c0 + j])));
                        float zg = 1.0f / (1.0f + __expf(-(acc[t][2 + nt][fi] + s_brz[128 + c0 + j])));
                        float ng = tanhf(acc[t][4 + nt][fi] + s_bin[c0 + j]
                                         + rg * (acc[t][6 + nt][fi] + s_bhn[c0 + j]));
                        o[j] = (1.0f - zg) * ng + zg * hh[j];
                    }
                    *(float2*)(out_mem + (long)node * H + c0) = make_float2(o[0], o[1]);
                }
            }
        }
    }

    if (tid < BM) {
        int r = row0 + tid;
        if (r < B) out_lu[s_nodes[tid]] = ts[r];
    }
}

// ---------------------------------------------------------------------------
// Launch. Inputs (metadata order):
//   0 memory [N,128] | 1 last_update [N] | 2 unique_node_ids [B] i32
//   3 unique_messages [B,256] | 4 timestamps [B]
//   5 W_ih [384,256] | 6 W_hh [384,128] | 7 b_ih [384] | 8 b_hh [384]
// Output: concat(updated_memory [N*128], updated_last_update [N]) f32
// ---------------------------------------------------------------------------
extern "C" void kernel_launch(void* const* d_in, const int* in_sizes, int n_in,
                              void* d_out, int out_size) {
    const float* memory      = (const float*)d_in[0];
    const float* last_update = (const float*)d_in[1];
    const int*   node_ids    = (const int*)  d_in[2];
    const float* X           = (const float*)d_in[3];
    const float* ts          = (const float*)d_in[4];
    const float* W_ih        = (const float*)d_in[5];
    const float* W_hh        = (const float*)d_in[6];
    const float* b_ih        = (const float*)d_in[7];
    const float* b_hh        = (const float*)d_in[8];

    const int n_nodes = in_sizes[1];
    const int B       = in_sizes[2];

    float* out_mem = (float*)d_out;
    float* out_lu  = out_mem + (long)n_nodes * H;

    // clone memory + last_update -> out (single launch)
    {
        long n4m = (long)n_nodes * H / 4;
        long n4l = (long)n_nodes / 4;
        clone_kernel<<<16384, 256>>>((const float4*)memory, (float4*)out_mem, n4m,
                                     (const float4*)last_update, (float4*)out_lu, n4l);
    }
    // fused fp16 mma GRU + scatter
    {
        cudaFuncSetAttribute(gru_mma_kernel,
                             cudaFuncAttributeMaxDynamicSharedMemorySize, SMEM_BYTES);
        int blocks = (B + BM - 1) / BM;
        gru_mma_kernel<<<blocks, NTHREADS, SMEM_BYTES>>>(memory, node_ids, X, ts,
                                                         W_ih, W_hh, b_ih, b_hh,
                                                         out_mem, out_lu, B);
    }
}